// round 5
// baseline (speedup 1.0000x reference)
#include <cuda_runtime.h>

#define NB 128
#define THREADS 1024
#define NITER 60
#define TSTRIDE 268      // floats per table row: 12*row %32 bank rotation, 16B aligned
#define COLOFF 132       // col-partial section offset (+4 banks vs row section)

typedef unsigned long long ull;

__device__ __forceinline__ ull pk2(float lo, float hi) {
    ull r; asm("mov.b64 %0, {%1, %2};" : "=l"(r) : "f"(lo), "f"(hi)); return r;
}
__device__ __forceinline__ void upk2(ull v, float& lo, float& hi) {
    asm("mov.b64 {%0, %1}, %2;" : "=f"(lo), "=f"(hi) : "l"(v));
}
__device__ __forceinline__ ull padd2(ull a, ull b) {
    ull r; asm("add.rn.f32x2 %0, %1, %2;" : "=l"(r) : "l"(a), "l"(b)); return r;
}
__device__ __forceinline__ ull psub2(ull a, ull b) {
    ull r; asm("sub.rn.f32x2 %0, %1, %2;" : "=l"(r) : "l"(a), "l"(b)); return r;
}

__global__ void __launch_bounds__(THREADS, 1)
gfusedmax_kernel(const float* __restrict__ x,
                 const float* __restrict__ A,
                 float* __restrict__ out)
{
    const int b     = blockIdx.x;
    const int tid   = threadIdx.x;
    const int lane  = tid & 31;
    const int warp  = tid >> 5;
    const int rbase = warp * 4;            // warp w owns rows 4w..4w+3

    __shared__ __align__(16) float tab[32][TSTRIDE];   // 34.3 KB partial table
    __shared__ __align__(16) float sy_row[NB];         // step * y
    __shared__ float ys_s[NB];
    __shared__ float sorted_s[NB];
    __shared__ float csum[2][NB];
    __shared__ int   rankp[8][NB];
    __shared__ float wsum[4], wcnt[4];

    const float step = 1.0f / 256.0f;

    // ---- clip bounds: lane L owns cols 4L..4L+3 (float4 loads, coalesced) ----
    float4 wv[4];
    ull z2[4][2];
    const float* Ab = A + (size_t)b * NB * NB;
    #pragma unroll
    for (int r = 0; r < 4; ++r) {
        wv[r] = *reinterpret_cast<const float4*>(&Ab[(size_t)(rbase + r) * NB + 4 * lane]);
        z2[r][0] = 0ULL;
        z2[r][1] = 0ULL;
    }

    // ---- phase-B identity: h = index-within-warp, sub = contributor slice ----
    const int h    = lane >> 2;            // 0..7 : h<4 -> row 4w+h, h>=4 -> col 4w+(h-4)
    const int sub  = lane & 3;
    const bool isRow = (h < 4);
    const int jidx = isRow ? (rbase + h) : (COLOFF + rbase + (h - 4));
    float xq = 0.0f;
    if (sub == 0 && isRow) {
        xq = x[(size_t)b * NB + rbase + h];
        sy_row[rbase + h] = step * xq;
    }
    __syncthreads();

    // ---- 60 projected-gradient iterations ----
    #pragma unroll 1
    for (int it = 0; it < NITER; ++it) {
        // ---- phase A: z update + per-lane partials (no shuffles) ----
        float4 sc4 = *reinterpret_cast<const float4*>(&sy_row[4 * lane]);   // LDS.128 c-free
        float4 s4  = *reinterpret_cast<const float4*>(&sy_row[rbase]);      // broadcast
        ull c2_0 = pk2(sc4.x, sc4.y);
        ull c2_1 = pk2(sc4.z, sc4.w);
        const float syr[4] = {s4.x, s4.y, s4.z, s4.w};

        ull ca0 = 0ULL, ca1 = 0ULL;
        float4 rv;
        float* rvp = &rv.x;

        #pragma unroll
        for (int r = 0; r < 4; ++r) {
            ull s2 = pk2(syr[r], syr[r]);
            // cols (4L, 4L+1)
            ull v0 = padd2(z2[r][0], psub2(s2, c2_0));
            float ax, ay; upk2(v0, ax, ay);
            ax = fminf(fmaxf(ax, -wv[r].x), wv[r].x);
            ay = fminf(fmaxf(ay, -wv[r].y), wv[r].y);
            ull zz0 = pk2(ax, ay);
            z2[r][0] = zz0;
            ca0 = padd2(ca0, zz0);
            // cols (4L+2, 4L+3)
            ull v1 = padd2(z2[r][1], psub2(s2, c2_1));
            float bx, by; upk2(v1, bx, by);
            bx = fminf(fmaxf(bx, -wv[r].z), wv[r].z);
            by = fminf(fmaxf(by, -wv[r].w), wv[r].w);
            ull zz1 = pk2(bx, by);
            z2[r][1] = zz1;
            ca1 = padd2(ca1, zz1);
            // row partial for row rbase+r (horizontal sum of 4 cols)
            ull rs2 = padd2(zz0, zz1);
            float rl, rh; upk2(rs2, rl, rh);
            rvp[r] = rl + rh;
        }

        // row partials: tab[lane][4w..4w+3]  (STS.128, conflict-free via stride 268)
        *reinterpret_cast<float4*>(&tab[lane][4 * warp]) = rv;
        // col partials: tab[warp][COLOFF + 4L..4L+3]  (STS.128, conflict-free)
        float4 cv;
        upk2(ca0, cv.x, cv.y);
        upk2(ca1, cv.z, cv.w);
        *reinterpret_cast<float4*>(&tab[warp][COLOFF + 4 * lane]) = cv;

        __syncthreads();

        // ---- phase B: 8 reductions/warp, 8 LDS + tree + 2 shfl + 1 shfl pair ----
        const float* p = &tab[sub * 8][jidx];
        float v0 = p[0 * TSTRIDE], v1 = p[1 * TSTRIDE];
        float v2 = p[2 * TSTRIDE], v3 = p[3 * TSTRIDE];
        float v4 = p[4 * TSTRIDE], v5 = p[5 * TSTRIDE];
        float v6 = p[6 * TSTRIDE], v7 = p[7 * TSTRIDE];
        float s = ((v0 + v1) + (v2 + v3)) + ((v4 + v5) + (v6 + v7));
        s += __shfl_xor_sync(0xffffffffu, s, 1);
        s += __shfl_xor_sync(0xffffffffu, s, 2);
        float other = __shfl_xor_sync(0xffffffffu, s, 16);  // pairs rs[i] with cs[i]

        if (sub == 0 && isRow) {
            float y = xq - s + other;
            sy_row[rbase + h] = step * y;
        }
        __syncthreads();
    }

    // ---- final y (exact: /256 then *256 is exponent-only) ----
    float yv = 0.0f;
    if (tid < NB) {
        yv = sy_row[tid] * 256.0f;
        ys_s[tid] = yv;
    }
    __syncthreads();

    // ---- sparsemax: parallel rank sort (branch-free, deterministic) ----
    {
        int i = tid & 127;
        int g = tid >> 7;                 // 8 groups of 16 comparisons
        float vi = ys_s[i];
        int rp = 0;
        #pragma unroll
        for (int jj = 0; jj < 16; ++jj) {
            int j = g * 16 + jj;
            float uj = ys_s[j];
            rp += (uj > vi) || (uj == vi && j < i);
        }
        rankp[g][i] = rp;
    }
    __syncthreads();
    if (tid < NB) {
        int rank = ((rankp[0][tid] + rankp[1][tid]) + (rankp[2][tid] + rankp[3][tid]))
                 + ((rankp[4][tid] + rankp[5][tid]) + (rankp[6][tid] + rankp[7][tid]));
        sorted_s[rank] = yv;              // descending
    }
    __syncthreads();

    // inclusive scan (Hillis-Steele, ping-pong)
    if (tid < NB) csum[0][tid] = sorted_s[tid];
    __syncthreads();
    int src = 0;
    for (int off = 1; off < NB; off <<= 1) {
        if (tid < NB) {
            float vv = csum[src][tid];
            if (tid >= off) vv += csum[src][tid - off];
            csum[1 - src][tid] = vv;
        }
        __syncthreads();
        src = 1 - src;
    }

    // mask + deterministic (sum, count) reduction (shuffle funnel — no f32 REDUX on sm_103a)
    if (tid < NB) {
        float s  = sorted_s[tid];
        float cu = csum[src][tid];
        float k  = (float)(tid + 1);
        bool  m  = (1.0f + k * s > cu);
        float sv = m ? s : 0.0f;
        float sc = m ? 1.0f : 0.0f;
        #pragma unroll
        for (int sft = 16; sft > 0; sft >>= 1) {
            sv += __shfl_xor_sync(0xffffffffu, sv, sft);
            sc += __shfl_xor_sync(0xffffffffu, sc, sft);
        }
        if (lane == 0) { wsum[warp] = sv; wcnt[warp] = sc; }
    }
    __syncthreads();

    if (tid < NB) {
        float ssum = ((wsum[0] + wsum[1]) + (wsum[2] + wsum[3]));
        float scnt = ((wcnt[0] + wcnt[1]) + (wcnt[2] + wcnt[3]));
        float tau  = (ssum - 1.0f) / scnt;
        out[(size_t)b * NB + tid] = fmaxf(yv - tau, 0.0f);
    }
}

extern "C" void kernel_launch(void* const* d_in, const int* in_sizes, int n_in,
                              void* d_out, int out_size)
{
    const float* x = (const float*)d_in[0];   // [B, 128]
    const float* A = (const float*)d_in[1];   // [B, 128, 128]
    float* out = (float*)d_out;               // [B, 128] float32

    int B = in_sizes[0] / NB;                 // 4096
    gfusedmax_kernel<<<B, THREADS>>>(x, A, out);
}

// round 7
// speedup vs baseline: 1.4336x; 1.4336x over previous
#include <cuda_runtime.h>

#define NB 128
#define THREADS 1024
#define NITER 60
#define TS_R 129        // rowtab stride (129 % 32 == 1), indices 0..127 -> no overflow
#define TS_C 131        // coltab stride (131 % 32 == 3), swizzled indices reach 130

typedef unsigned long long ull;

__device__ __forceinline__ ull pk2(float lo, float hi) {
    ull r; asm("mov.b64 %0, {%1, %2};" : "=l"(r) : "f"(lo), "f"(hi)); return r;
}
__device__ __forceinline__ void upk2(ull v, float& lo, float& hi) {
    asm("mov.b64 {%0, %1}, %2;" : "=f"(lo), "=f"(hi) : "l"(v));
}
__device__ __forceinline__ ull padd2(ull a, ull b) {
    ull r; asm("add.rn.f32x2 %0, %1, %2;" : "=l"(r) : "l"(a), "l"(b)); return r;
}
__device__ __forceinline__ ull psub2(ull a, ull b) {
    ull r; asm("sub.rn.f32x2 %0, %1, %2;" : "=l"(r) : "l"(a), "l"(b)); return r;
}

__global__ void __launch_bounds__(THREADS, 1)
gfusedmax_kernel(const float* __restrict__ x,
                 const float* __restrict__ A,
                 float* __restrict__ out)
{
    const int b     = blockIdx.x;
    const int tid   = threadIdx.x;
    const int lane  = tid & 31;
    const int warp  = tid >> 5;
    const int rbase = warp * 4;            // warp w owns rows 4w..4w+3; lane L owns cols 4L..4L+3

    __shared__ float rowtab[32 * TS_R];            // [contrib lane][row j]
    __shared__ float coltab[32 * TS_C];            // [contrib warp][swz(col j)]
    __shared__ __align__(16) float sy_row[NB];     // step * y
    __shared__ float ys_s[NB];
    __shared__ float sorted_s[NB];
    __shared__ float csum[2][NB];
    __shared__ int   rankp[8][NB];
    __shared__ float wsum[4], wcnt[4];

    const float step = 1.0f / 256.0f;

    // ---- clip bounds: lane L owns cols 4L..4L+3 (float4 loads, coalesced) ----
    float4 wv[4];
    ull z2[4][2];
    const float* Ab = A + (size_t)b * NB * NB;
    #pragma unroll
    for (int r = 0; r < 4; ++r) {
        wv[r] = *reinterpret_cast<const float4*>(&Ab[(size_t)(rbase + r) * NB + 4 * lane]);
        z2[r][0] = 0ULL;
        z2[r][1] = 0ULL;
    }

    // ---- phase-B identity: j = tid>>3 (target index), g = tid&7 (contributor group) ----
    const int j  = tid >> 3;
    const int g  = tid & 7;
    const int sj = j + (j >> 5);                   // swizzled column index (max 130)
    const float xq = x[(size_t)b * NB + j];        // 8-lane broadcast load, coalesced

    // phase-A store addresses (precomputed)
    float* rw = &rowtab[lane * TS_R + 4 * warp];                 // rowtab[lane][4w + r]
    float* cw = &coltab[warp * TS_C + 4 * lane + (lane >> 3)];   // coltab[warp][swz(4L + c)]
    // phase-B load bases
    const float* rrd = &rowtab[(4 * g) * TS_R + j];
    const float* crd = &coltab[(4 * g) * TS_C + sj];

    if (g == 0) sy_row[j] = step * xq;
    __syncthreads();

    // ---- 60 projected-gradient iterations ----
    #pragma unroll 1
    for (int it = 0; it < NITER; ++it) {
        // ===== phase A: z update + per-(lane,warp) partials, zero shuffles =====
        float4 sc4 = *reinterpret_cast<const float4*>(&sy_row[4 * lane]);  // LDS.128 c-free
        float4 s4  = *reinterpret_cast<const float4*>(&sy_row[rbase]);     // broadcast
        ull c2_0 = pk2(sc4.x, sc4.y);
        ull c2_1 = pk2(sc4.z, sc4.w);
        const float syr[4] = {s4.x, s4.y, s4.z, s4.w};

        ull ca0 = 0ULL, ca1 = 0ULL;
        float rv[4];

        #pragma unroll
        for (int r = 0; r < 4; ++r) {
            ull s2 = pk2(syr[r], syr[r]);
            // cols (4L, 4L+1)
            ull v0 = padd2(z2[r][0], psub2(s2, c2_0));
            float ax, ay; upk2(v0, ax, ay);
            ax = fminf(fmaxf(ax, -wv[r].x), wv[r].x);
            ay = fminf(fmaxf(ay, -wv[r].y), wv[r].y);
            ull zz0 = pk2(ax, ay);
            z2[r][0] = zz0;
            ca0 = padd2(ca0, zz0);
            // cols (4L+2, 4L+3)
            ull v1 = padd2(z2[r][1], psub2(s2, c2_1));
            float bx, by; upk2(v1, bx, by);
            bx = fminf(fmaxf(bx, -wv[r].z), wv[r].z);
            by = fminf(fmaxf(by, -wv[r].w), wv[r].w);
            ull zz1 = pk2(bx, by);
            z2[r][1] = zz1;
            ca1 = padd2(ca1, zz1);
            // row partial: horizontal sum of this lane's 4 cols in row rbase+r
            ull rs2 = padd2(zz0, zz1);
            float rl, rh; upk2(rs2, rl, rh);
            rv[r] = rl + rh;
        }

        // row partials: bank = lane + 4w + r  -> conflict-free scalar stores
        rw[0] = rv[0]; rw[1] = rv[1]; rw[2] = rv[2]; rw[3] = rv[3];
        // col partials: bank = 3w + 4L + c + (L>>3) -> conflict-free scalar stores
        {
            float c0v, c1v, c2v, c3v;
            upk2(ca0, c0v, c1v);
            upk2(ca1, c2v, c3v);
            cw[0] = c0v; cw[1] = c1v; cw[2] = c2v; cw[3] = c3v;
        }
        __syncthreads();

        // ===== phase B: every thread reduces 4 contributors for target j =====
        float r0 = rrd[0 * TS_R], r1 = rrd[1 * TS_R], r2 = rrd[2 * TS_R], r3 = rrd[3 * TS_R];
        float c0 = crd[0 * TS_C], c1 = crd[1 * TS_C], c2 = crd[2 * TS_C], c3 = crd[3 * TS_C];
        float d = ((c0 - r0) + (c1 - r1)) + ((c2 - r2) + (c3 - r3));
        d += __shfl_xor_sync(0xffffffffu, d, 1);
        d += __shfl_xor_sync(0xffffffffu, d, 2);
        d += __shfl_xor_sync(0xffffffffu, d, 4);
        if (g == 0) sy_row[j] = step * (xq + d);     // y = x - rowsum + colsum
        __syncthreads();
    }

    // ---- final y (exact: /256 then *256 is exponent-only) ----
    float yv = 0.0f;
    if (tid < NB) {
        yv = sy_row[tid] * 256.0f;
        ys_s[tid] = yv;
    }
    __syncthreads();

    // ---- sparsemax: parallel rank sort (branch-free, deterministic) ----
    {
        int i = tid & 127;
        int gg = tid >> 7;                // 8 groups of 16 comparisons
        float vi = ys_s[i];
        int rp = 0;
        #pragma unroll
        for (int jj = 0; jj < 16; ++jj) {
            int jc = gg * 16 + jj;
            float uj = ys_s[jc];
            rp += (uj > vi) || (uj == vi && jc < i);
        }
        rankp[gg][i] = rp;
    }
    __syncthreads();
    if (tid < NB) {
        int rank = ((rankp[0][tid] + rankp[1][tid]) + (rankp[2][tid] + rankp[3][tid]))
                 + ((rankp[4][tid] + rankp[5][tid]) + (rankp[6][tid] + rankp[7][tid]));
        sorted_s[rank] = yv;              // descending
    }
    __syncthreads();

    // inclusive scan (Hillis-Steele, ping-pong)
    if (tid < NB) csum[0][tid] = sorted_s[tid];
    __syncthreads();
    int src = 0;
    for (int off = 1; off < NB; off <<= 1) {
        if (tid < NB) {
            float vv = csum[src][tid];
            if (tid >= off) vv += csum[src][tid - off];
            csum[1 - src][tid] = vv;
        }
        __syncthreads();
        src = 1 - src;
    }

    // mask + deterministic (sum, count) reduction (no f32 REDUX on sm_103a)
    if (tid < NB) {
        float s  = sorted_s[tid];
        float cu = csum[src][tid];
        float k  = (float)(tid + 1);
        bool  m  = (1.0f + k * s > cu);
        float sv = m ? s : 0.0f;
        float sc = m ? 1.0f : 0.0f;
        #pragma unroll
        for (int sft = 16; sft > 0; sft >>= 1) {
            sv += __shfl_xor_sync(0xffffffffu, sv, sft);
            sc += __shfl_xor_sync(0xffffffffu, sc, sft);
        }
        if (lane == 0) { wsum[warp] = sv; wcnt[warp] = sc; }
    }
    __syncthreads();

    if (tid < NB) {
        float ssum = ((wsum[0] + wsum[1]) + (wsum[2] + wsum[3]));
        float scnt = ((wcnt[0] + wcnt[1]) + (wcnt[2] + wcnt[3]));
        float tau  = (ssum - 1.0f) / scnt;
        out[(size_t)b * NB + tid] = fmaxf(yv - tau, 0.0f);
    }
}

extern "C" void kernel_launch(void* const* d_in, const int* in_sizes, int n_in,
                              void* d_out, int out_size)
{
    const float* x = (const float*)d_in[0];   // [B, 128]
    const float* A = (const float*)d_in[1];   // [B, 128, 128]
    float* out = (float*)d_out;               // [B, 128] float32

    int B = in_sizes[0] / NB;                 // 4096
    gfusedmax_kernel<<<B, THREADS>>>(x, A, out);
}